// round 11
// baseline (speedup 1.0000x reference)
#include <cuda_runtime.h>
#include <cstdint>

// Problem shape (fixed by setup_inputs): B=256, T=512, C=1024, L=64, S=129
#define Bv 256
#define Tv 512
#define Cv 1024
#define Lv 64
#define EPS 1e-7f
#define PD 16             // DP demand-ring depth for rows [0,RING)
#define RING 128          // rows the DP warp loads itself (global ring)
#define CK 48             // rows per preload chunk
#define NCK 8             // chunks: 8*48 = 384 = Tv-RING
#define ROWF 66           // smem row stride (floats): 64 labels + blank + pad
#define BOOST 100         // rescale target: warp max -> 2^BOOST (underflow margin)

#define SMEM_BYTES ((Tv - RING) * ROWF * 4)   // 101376 B dynamic

// ---------------------------------------------------------------------------
// Hybrid fused CTC forward. One CTA (4 warps) per batch row.
//   warp 0  : DP (identical math to the 72.4us R3 kernel). Rows [0,128) come
//             from its own PD=16 global register ring; rows [128,512) from smem.
//   warps1-3: preloaders. 8 chunks x 48 rows into dynamic smem; per chunk each
//             thread issues 16 independent LDG pairs into register arrays
//             BEFORE any STS (true MLP ~32/thread, ~3k/CTA -> DRAM saturates;
//             the R4/R7 loader failures were LDG->STS serialization).
// Sync: one __syncthreads() per chunk. Preloader: load chunk c, bar. DP: 128
// ring steps, then per chunk: bar, consume. Barrier drains STS -> data visible.
// DP state: lane l owns states {4l..4l+3}; lane 31 also state 128. Even states
// are blank (no s-2 skip) -> ONE shfl_up per step. Linear-domain recurrence +
// exact power-of-2 rescale (exponent surgery, warp-max pipelined, period 4).
// ---------------------------------------------------------------------------
__global__ void __launch_bounds__(128) ctc_hybrid_kernel(const int* __restrict__ y_true,
                                                         const float* __restrict__ y_pred,
                                                         float* __restrict__ out) {
    extern __shared__ float sm[];          // [Tv-RING][ROWF]
    __shared__ int lab_sm[Lv];

    int b   = blockIdx.x;
    int tid = threadIdx.x;
    int wid = tid >> 5;
    int l   = tid & 31;

    if (tid < Lv) lab_sm[tid] = y_true[b * Lv + tid];
    __syncthreads();

    const float* bp = y_pred + (size_t)b * Tv * Cv;
    int c0 = lab_sm[2 * l];
    int c1 = lab_sm[2 * l + 1];

    if (wid >= 1) {
        // ---------------- preloader warps (1..3) ----------------
        int p = wid - 1;                   // 0..2
        for (int c = 0; c < NCK; c++) {
            int rbase = RING + c * CK + p * 16;
            float va[16], vb[16], vk[16];
#pragma unroll
            for (int k = 0; k < 16; k++) {
                const float* g = bp + (size_t)(rbase + k) * Cv;
                va[k] = g[c0];
                vb[k] = g[c1];
                if (l == 31) vk[k] = g[Cv - 1];        // blank = last class
            }
#pragma unroll
            for (int k = 0; k < 16; k++) {
                float* row = sm + (rbase + k - RING) * ROWF;
                *(float2*)(row + 2 * l) = make_float2(va[k], vb[k]);
                if (l == 31) row[64] = vk[k];
            }
            __syncthreads();               // chunk c visible to DP
        }
    } else {
        // ---------------- DP warp ----------------
        int cm1 = __shfl_up_sync(0xffffffffu, c1, 1);
        bool al1 = (l > 0) && (c0 != cm1);   // skip into state 4l+1
        bool al3 = (c1 != c0);               // skip into state 4l+3

        const float* p0 = bp + c0;
        const float* p1 = bp + c1;
        const float* pB = bp + (Cv - 1);

        // global demand ring for rows [0, RING)
        float f0[PD], f1[PD], fb[PD];
#pragma unroll
        for (int i = 0; i < PD; i++) {
            f0[i] = p0[i * Cv];
            f1[i] = p1[i * Cv];
            fb[i] = pB[i * Cv];
        }

        float a0 = 0.f, a1 = 0.f, a2 = 0.f, a3 = 0.f, a4 = 0.f;
        float r  = 1.0f;
        int   esc = 0;   // alpha_true = a * 2^esc (identical on all lanes)

        // ---- phase A: rows 0..RING-1 from the ring ----
#pragma unroll 16
        for (int t = 0; t < RING; t++) {
            int bi = t & (PD - 1);
            float px = f0[bi] + EPS;
            float py = f1[bi] + EPS;
            float pb = fb[bi] + EPS;

            if (t == 0) {
                if (l == 0) { a0 = pb; a1 = px; }
            } else {
                float pa3 = __shfl_up_sync(0xffffffffu, a3, 1);
                if (l == 0) pa3 = 0.f;
                float n0 = (a0 + pa3) * pb;
                float n1 = (a1 + a0 + (al1 ? pa3 : 0.f)) * px;
                float n2 = (a2 + a1) * pb;
                float n3 = (a3 + a2 + (al3 ? a1 : 0.f)) * py;
                float n4 = (l == 31) ? (a4 + a3) * pb : 0.f;
                a0 = n0; a1 = n1; a2 = n2; a3 = n3; a4 = n4;
            }
            int tn = t + PD;
            if (tn < RING) {
                f0[bi] = p0[tn * Cv];
                f1[bi] = p1[tn * Cv];
                fb[bi] = pB[tn * Cv];
            }
            int ph = t & 3;
            if (ph == 0) {
                r = fmaxf(fmaxf(a0, a1), fmaxf(a2, a3));
                if (l == 31) r = fmaxf(r, a4);
                r = fmaxf(r, __shfl_xor_sync(0xffffffffu, r, 1));
            } else if (ph == 1) {
                r = fmaxf(r, __shfl_xor_sync(0xffffffffu, r, 2));
                r = fmaxf(r, __shfl_xor_sync(0xffffffffu, r, 4));
            } else if (ph == 2) {
                r = fmaxf(r, __shfl_xor_sync(0xffffffffu, r, 8));
                r = fmaxf(r, __shfl_xor_sync(0xffffffffu, r, 16));
            } else {
                int eb = (__float_as_int(r) >> 23) & 0xff;
                int se = 254 - eb + BOOST;
                se = se > 254 ? 254 : se;
                float sc = __int_as_float(se << 23);
                a0 *= sc; a1 *= sc; a2 *= sc; a3 *= sc; a4 *= sc;
                esc += 127 - se;
            }
        }

        // ---- phase B: rows RING..Tv-1 from smem, chunk by chunk ----
        for (int c = 0; c < NCK; c++) {
            __syncthreads();               // chunk c ready
            const float* ck = sm + c * CK * ROWF;
            float2 pv  = *(const float2*)(ck + 2 * l);
            float  pbv = ck[64];
#pragma unroll 8
            for (int tl = 0; tl < CK; tl++) {
                float px = pv.x + EPS;
                float py = pv.y + EPS;
                float pb = pbv  + EPS;
                if (tl < CK - 1) {
                    pv  = *(const float2*)(ck + (tl + 1) * ROWF + 2 * l);
                    pbv = ck[(tl + 1) * ROWF + 64];
                }
                int t = RING + c * CK + tl;
                {
                    float pa3 = __shfl_up_sync(0xffffffffu, a3, 1);
                    if (l == 0) pa3 = 0.f;
                    float n0 = (a0 + pa3) * pb;
                    float n1 = (a1 + a0 + (al1 ? pa3 : 0.f)) * px;
                    float n2 = (a2 + a1) * pb;
                    float n3 = (a3 + a2 + (al3 ? a1 : 0.f)) * py;
                    float n4 = (l == 31) ? (a4 + a3) * pb : 0.f;
                    a0 = n0; a1 = n1; a2 = n2; a3 = n3; a4 = n4;
                }
                int ph = t & 3;
                if (ph == 0) {
                    r = fmaxf(fmaxf(a0, a1), fmaxf(a2, a3));
                    if (l == 31) r = fmaxf(r, a4);
                    r = fmaxf(r, __shfl_xor_sync(0xffffffffu, r, 1));
                } else if (ph == 1) {
                    r = fmaxf(r, __shfl_xor_sync(0xffffffffu, r, 2));
                    r = fmaxf(r, __shfl_xor_sync(0xffffffffu, r, 4));
                } else if (ph == 2) {
                    r = fmaxf(r, __shfl_xor_sync(0xffffffffu, r, 8));
                    r = fmaxf(r, __shfl_xor_sync(0xffffffffu, r, 16));
                } else {
                    int eb = (__float_as_int(r) >> 23) & 0xff;
                    int se = 254 - eb + BOOST;
                    se = se > 254 ? 254 : se;
                    float sc = __int_as_float(se << 23);
                    a0 *= sc; a1 *= sc; a2 *= sc; a3 *= sc; a4 *= sc;
                    esc += 127 - se;
                }
            }
        }

        // ll = 64 -> loss from states 128 (a4) and 127 (a3), lane 31
        if (l == 31) {
            float s = a4 + a3;
            out[b] = -(logf(s) + (float)esc * 0.69314718055994531f);
        }
    }
}

extern "C" void kernel_launch(void* const* d_in, const int* in_sizes, int n_in,
                              void* d_out, int out_size) {
    const int*   y_true = (const int*)d_in[0];    // [256, 64] int32
    const float* y_pred = (const float*)d_in[1];  // [256, 512, 1024] float32
    float*       out    = (float*)d_out;          // [256, 1] float32

    cudaFuncSetAttribute(ctc_hybrid_kernel,
                         cudaFuncAttributeMaxDynamicSharedMemorySize, SMEM_BYTES);
    ctc_hybrid_kernel<<<Bv, 128, SMEM_BYTES>>>(y_true, y_pred, out);
}